// round 12
// baseline (speedup 1.0000x reference)
#include <cuda_runtime.h>
#include <math.h>

#define BATCH 8192
#define FULL 0xffffffffu
#define RB 32                      // rows per block in main GEMM
#define NBLK (BATCH / RB)          // 256

// Scratch (no allocation allowed -> device globals)
__device__ float2 g_Wri[256 * 256];   // [k][a] = (Ur[a][k], Ui[a][k])   512KB
__device__ float  g_Wf[256 * 64];     // [k][c] = fW1[c][k]
__device__ float  g_h[BATCH * 4];     // fused pre-cW1 hidden (qf+cf)
__device__ float  g_h2[BATCH * 16];
__device__ float  g_part1[NBLK * 16]; // per-block: 14 h-moments
__device__ float  g_part2[256 * 32];  // per-bn1-block: sum[16], sumsq[16]
__device__ float4 g_fw1[32];          // BN1-fused cW1 rows
__device__ float  g_fb1[32];          // BN1-fused bias
__device__ float  g_ab2[32];          // alpha2[16], beta2[16]
__device__ int    g_ctr1, g_ctr2;     // last-block counters (zeroed by prep)

// ---------------------------------------------------------------------------
// packed f32x2 helpers (sm_100+/sm_103a)
// ---------------------------------------------------------------------------
#define PACK2(d, v) asm("mov.b64 %0,{%1,%1};" : "=l"(d) : "f"(v))
#define FMA2(acc, a, b) \
    asm("fma.rn.f32x2 %0,%1,%2,%0;" : "+l"(acc) : "l"(a), "l"(b))
#define UNPK(lo, hi, v) asm("mov.b64 {%0,%1},%2;" : "=f"(lo), "=f"(hi) : "l"(v))

// ---------------------------------------------------------------------------
// CNOT helpers (state: sr[8]/si[8] per lane; lane = amp bits 7..3)
// ---------------------------------------------------------------------------
#define CNOT_LL(cm, tm)                                                        \
    {                                                                          \
        _Pragma("unroll") for (int j = 0; j < 8; j++) {                        \
            float orr = __shfl_xor_sync(FULL, sr[j], (tm));                    \
            float ori = __shfl_xor_sync(FULL, si[j], (tm));                    \
            if (lane & (cm)) { sr[j] = orr; si[j] = ori; }                     \
        }                                                                      \
    }

#define CNOT_LT(cm, mb)                                                        \
    {                                                                          \
        bool f = (lane & (cm)) != 0;                                           \
        _Pragma("unroll") for (int j = 0; j < 8; j++) {                        \
            if (j & (mb)) continue;                                            \
            int j1 = j | (mb);                                                 \
            float t0r = sr[j], t0i = si[j];                                    \
            sr[j] = f ? sr[j1] : sr[j];                                        \
            si[j] = f ? si[j1] : si[j];                                        \
            sr[j1] = f ? t0r : sr[j1];                                         \
            si[j1] = f ? t0i : si[j1];                                         \
        }                                                                      \
    }

#define CNOT_TL(mb, tm)                                                        \
    {                                                                          \
        _Pragma("unroll") for (int j = 0; j < 8; j++) {                        \
            if (!(j & (mb))) continue;                                         \
            sr[j] = __shfl_xor_sync(FULL, sr[j], (tm));                        \
            si[j] = __shfl_xor_sync(FULL, si[j], (tm));                        \
        }                                                                      \
    }

#define CNOT_TT(cmb, tmb)                                                      \
    {                                                                          \
        _Pragma("unroll") for (int j = 0; j < 8; j++) {                        \
            if (!((j & (cmb)) && !(j & (tmb)))) continue;                      \
            int j1 = j | (tmb);                                                \
            float tr = sr[j]; sr[j] = sr[j1]; sr[j1] = tr;                     \
            float ti = si[j]; si[j] = si[j1]; si[j1] = ti;                     \
        }                                                                      \
    }

// ---------------------------------------------------------------------------
// Prep: blocks 0..31 compute the circuit unitary U column-by-column;
// block 32 transposes fW1 and zeroes the last-block counters.
// ---------------------------------------------------------------------------
__global__ void __launch_bounds__(256) prep_kernel(const float* __restrict__ qw,
                                                   const float* __restrict__ fW1) {
    int t = threadIdx.x;
    if (blockIdx.x == 32) {
        if (t == 0) { g_ctr1 = 0; g_ctr2 = 0; }
        for (int idx = t; idx < 64 * 256; idx += 256) {
            int c = idx >> 8, k = idx & 255;
            g_Wf[k * 64 + c] = fW1[idx];
        }
        return;
    }

    __shared__ float s_U[48 * 8];
    if (t < 48) {
        int l = t / 8, q = t % 8;
        float ax = qw[l * 24 + 3 * q + 0] * 0.5f;
        float ay = qw[l * 24 + 3 * q + 1] * 0.5f;
        float az = qw[l * 24 + 3 * q + 2] * 0.5f;
        float cx, sx, cy, sy, cz, sz;
        sincosf(ax, &sx, &cx);
        sincosf(ay, &sy, &cy);
        sincosf(az, &sz, &cz);
        float m00r = cy * cx, m00i = sy * sx;
        float m01r = -sy * cx, m01i = -cy * sx;
        float m10r = sy * cx, m10i = -cy * sx;
        float m11r = cy * cx, m11i = -sy * sx;
        float* u = &s_U[t * 8];
        u[0] = cz * m00r + sz * m00i;  u[1] = cz * m00i - sz * m00r;
        u[2] = cz * m01r + sz * m01i;  u[3] = cz * m01i - sz * m01r;
        u[4] = cz * m10r - sz * m10i;  u[5] = cz * m10i + sz * m10r;
        u[6] = cz * m11r - sz * m11i;  u[7] = cz * m11i + sz * m11r;
    }
    __syncthreads();

    int lane = t & 31;
    int wid = t >> 5;
    int kcol = blockIdx.x * 8 + wid;

    float sr[8], si[8];
#pragma unroll
    for (int j = 0; j < 8; j++) {
        sr[j] = (lane * 8 + j == kcol) ? 1.f : 0.f;
        si[j] = 0.f;
    }

#pragma unroll 1
    for (int l = 0; l < 6; l++) {
        const float* Ul = &s_U[l * 64];
        for (int q = 0; q < 5; q++) {
            const float* u = &Ul[q * 8];
            int m = 16 >> q;
            bool hi = (lane & m) != 0;
            float csr = hi ? u[6] : u[0], csi = hi ? u[7] : u[1];
            float cor = hi ? u[4] : u[2], coi = hi ? u[5] : u[3];
#pragma unroll
            for (int j = 0; j < 8; j++) {
                float orr = __shfl_xor_sync(FULL, sr[j], m);
                float ori = __shfl_xor_sync(FULL, si[j], m);
                float nr = csr * sr[j] - csi * si[j] + cor * orr - coi * ori;
                float ni = csr * si[j] + csi * sr[j] + cor * ori + coi * orr;
                sr[j] = nr; si[j] = ni;
            }
        }
#pragma unroll
        for (int q = 5; q < 8; q++) {
            const float* u = &Ul[q * 8];
            int mb = 1 << (7 - q);
#pragma unroll
            for (int j = 0; j < 8; j++) {
                if (j & mb) continue;
                int j1 = j | mb;
                float ar = sr[j], ai = si[j], br = sr[j1], bi = si[j1];
                sr[j]  = u[0] * ar - u[1] * ai + u[2] * br - u[3] * bi;
                si[j]  = u[0] * ai + u[1] * ar + u[2] * bi + u[3] * br;
                sr[j1] = u[4] * ar - u[5] * ai + u[6] * br - u[7] * bi;
                si[j1] = u[4] * ai + u[5] * ar + u[6] * bi + u[7] * br;
            }
        }
        CNOT_LL(16, 8);
        CNOT_LL(8, 4);
        CNOT_LL(4, 2);
        CNOT_LL(2, 1);
        CNOT_LT(1, 4);
        CNOT_TT(4, 2);
        CNOT_TT(2, 1);
        CNOT_TL(1, 16);
        CNOT_LL(16, 4);
        CNOT_LL(4, 1);
        CNOT_LT(1, 2);
    }

#pragma unroll
    for (int j = 0; j < 8; j++)
        g_Wri[kcol * 256 + lane * 8 + j] = make_float2(sr[j], si[j]);
}

// ---------------------------------------------------------------------------
// Main fused kernel: GEMM x@[Ur|Ui] + x@fW1^T (row-partitioned) + quantum
// epilogue + adapter + feature head -> g_h + h-moment partials.
// Last-finishing block combines the moments and emits BN1-fused weights.
// ---------------------------------------------------------------------------
__global__ void __launch_bounds__(256, 2) main_kernel(
    const float* __restrict__ x,
    const float* __restrict__ aW, const float* __restrict__ ab,
    const float* __restrict__ fb1,
    const float* __restrict__ fW2, const float* __restrict__ fb2,
    const float* __restrict__ cW1, const float* __restrict__ cb1,
    const float* __restrict__ g1, const float* __restrict__ be1)
{
    __shared__ __align__(16) float xs[256 * RB];   // transposed [k][r]  32KB
    __shared__ float s0s[8][RB], s1s[8][RB];
    __shared__ float fpart[8][4][8];               // [warp][i][local row]
    __shared__ float zs[RB][4], cfs[RB][4], hs[RB][4];
    __shared__ double mom[14];
    __shared__ int isLast;

    int t = threadIdx.x;
    int base = blockIdx.x * RB;

    // coalesced load of RB rows of x, store transposed [k][r]
    const float4* xg = (const float4*)(x + base * 256);
#pragma unroll
    for (int i = 0; i < (RB * 64) / 256; i++) {
        int g = t + 256 * i;
        float4 v = xg[g];
        int r = g >> 6;
        int k4 = (g & 63) * 4;
        xs[(k4 + 0) * RB + r] = v.x;
        xs[(k4 + 1) * RB + r] = v.y;
        xs[(k4 + 2) * RB + r] = v.z;
        xs[(k4 + 3) * RB + r] = v.w;
    }
    __syncthreads();

    int fc = t & 63;
    int rg = t >> 6;       // row group (8 rows) this thread owns for feature

    unsigned long long accR[16], accI[16], accF[4];
#pragma unroll
    for (int p = 0; p < 16; p++) { accR[p] = 0ull; accI[p] = 0ull; }
#pragma unroll
    for (int p = 0; p < 4; p++) accF[p] = 0ull;

#pragma unroll 2
    for (int k = 0; k < 256; k++) {
        float2 w = g_Wri[k * 256 + t];
        float wf = g_Wf[k * 64 + fc];
        unsigned long long wr2, wi2, wf2;
        PACK2(wr2, w.x);
        PACK2(wi2, w.y);
        PACK2(wf2, wf);
        const ulonglong2* xp = (const ulonglong2*)(xs + k * RB);
        {
            ulonglong2 xfa = xp[2 * rg];
            ulonglong2 xfb = xp[2 * rg + 1];
            FMA2(accF[0], wf2, xfa.x);
            FMA2(accF[1], wf2, xfa.y);
            FMA2(accF[2], wf2, xfb.x);
            FMA2(accF[3], wf2, xfb.y);
        }
#pragma unroll
        for (int q = 0; q < 8; q++) {
            ulonglong2 xv = xp[q];
            FMA2(accR[2 * q], wr2, xv.x);
            FMA2(accI[2 * q], wi2, xv.x);
            FMA2(accR[2 * q + 1], wr2, xv.y);
            FMA2(accI[2 * q + 1], wi2, xv.y);
        }
    }

    int lane = t & 31;
    int wid = t >> 5;

    float prob[RB];
#pragma unroll
    for (int p = 0; p < 16; p++) {
        float r0, r1, i0, i1;
        UNPK(r0, r1, accR[p]);
        UNPK(i0, i1, accI[p]);
        prob[2 * p]     = r0 * r0 + i0 * i0;
        prob[2 * p + 1] = r1 * r1 + i1 * i1;
    }

    float sgn = (lane & 16) ? -1.f : 1.f;
#pragma unroll
    for (int r = 0; r < RB; r++) {
        float a = prob[r], b = sgn * prob[r];
#pragma unroll
        for (int o = 16; o; o >>= 1) {
            a += __shfl_xor_sync(FULL, a, o);
            b += __shfl_xor_sync(FULL, b, o);
        }
        if (lane == 0) { s0s[wid][r] = a; s1s[wid][r] = b; }
    }

    // feature: relu then contract with fW2
    {
        float fb = fb1[fc];
        float fr[8];
#pragma unroll
        for (int p = 0; p < 4; p++) {
            float f0, f1;
            UNPK(f0, f1, accF[p]);
            fr[2 * p]     = fmaxf(f0 + fb, 0.f);
            fr[2 * p + 1] = fmaxf(f1 + fb, 0.f);
        }
#pragma unroll
        for (int i = 0; i < 4; i++) {
            float w2 = fW2[i * 64 + fc];
#pragma unroll
            for (int j = 0; j < 8; j++) {
                float v = fr[j] * w2;
#pragma unroll
                for (int o = 16; o; o >>= 1) v += __shfl_xor_sync(FULL, v, o);
                if (lane == 0) fpart[wid][i][j] = v;
            }
        }
    }
    __syncthreads();

    if (t < RB * 4) {
        int r = t & (RB - 1), i = t >> 5;
        float S = 0.f, acc = 0.f;
        if (i < 3) {
#pragma unroll
            for (int w = 0; w < 8; w++) {
                float v = s0s[w][r];
                S += v;
                acc += ((w >> (2 - i)) & 1) ? -v : v;
            }
        } else {
#pragma unroll
            for (int w = 0; w < 8; w++) {
                S += s0s[w][r];
                acc += s1s[w][r];
            }
        }
        zs[r][i] = acc / S;
        int wg = 2 * (r >> 3), jj = r & 7;
        cfs[r][i] = tanhf(fpart[wg][i][jj] + fpart[wg + 1][i][jj] + fb2[i]);
    }
    __syncthreads();
    if (t < RB * 4) {
        int r = t & (RB - 1), i = t >> 5;
        hs[r][i] = ab[i] + aW[i * 4 + 0] * zs[r][0] + aW[i * 4 + 1] * zs[r][1]
                         + aW[i * 4 + 2] * zs[r][2] + aW[i * 4 + 3] * zs[r][3]
                 + cfs[r][i];
    }
    __syncthreads();

    // warp 0: write h + 14 h-moment partials (fixed-order trees; lane 0 writes)
    if (t < 32) {
        float h0 = hs[t][0], h1 = hs[t][1], h2 = hs[t][2], h3 = hs[t][3];
        ((float4*)g_h)[base + t] = make_float4(h0, h1, h2, h3);
        float m[14] = {h0, h1, h2, h3,
                       h0 * h0, h0 * h1, h0 * h2, h0 * h3,
                       h1 * h1, h1 * h2, h1 * h3,
                       h2 * h2, h2 * h3, h3 * h3};
#pragma unroll
        for (int v = 0; v < 14; v++) {
            float s = m[v];
#pragma unroll
            for (int o = 16; o; o >>= 1) s += __shfl_xor_sync(FULL, s, o);
            if (lane == 0) g_part1[blockIdx.x * 16 + v] = s;
        }
    }

    // last-block detection (t==0 wrote the partials above -> its fence covers them)
    if (t == 0) {
        __threadfence();
        int old = atomicAdd(&g_ctr1, 1);
        isLast = (old == NBLK - 1);
    }
    __syncthreads();
    if (!isLast) return;
    __threadfence();

    // combine1: fp64 reduce 14 moments over 256 blocks (8 warps cover 14)
    {
        for (int m = wid; m < 14; m += 8) {
            double s = 0.0;
#pragma unroll
            for (int i = 0; i < NBLK / 32; i++)
                s += (double)g_part1[(lane + 32 * i) * 16 + m];
#pragma unroll
            for (int o = 16; o; o >>= 1) s += __shfl_xor_sync(FULL, s, o);
            if (lane == 0) mom[m] = s;
        }
    }
    __syncthreads();
    if (t < 32) {
        double invB = 1.0 / BATCH;
        double mu[4];
#pragma unroll
        for (int i = 0; i < 4; i++) mu[i] = mom[i] * invB;
        double C[4][4];
        const int pi[10] = {0, 0, 0, 0, 1, 1, 1, 2, 2, 3};
        const int pj[10] = {0, 1, 2, 3, 1, 2, 3, 2, 3, 3};
#pragma unroll
        for (int p = 0; p < 10; p++) {
            double c = mom[4 + p] * invB - mu[pi[p]] * mu[pj[p]];
            C[pi[p]][pj[p]] = c;
            C[pj[p]][pi[p]] = c;
        }
        double w[4];
#pragma unroll
        for (int i = 0; i < 4; i++) w[i] = (double)cW1[t * 4 + i];
        double mean = (double)cb1[t];
        double var = 0.0;
#pragma unroll
        for (int i = 0; i < 4; i++) {
            mean += w[i] * mu[i];
#pragma unroll
            for (int j = 0; j < 4; j++) var += w[i] * w[j] * C[i][j];
        }
        float alpha = g1[t] * rsqrtf((float)var + 1e-5f);
        float4 w1 = ((const float4*)cW1)[t];
        g_fw1[t] = make_float4(alpha * w1.x, alpha * w1.y, alpha * w1.z, alpha * w1.w);
        g_fb1[t] = alpha * ((float)((double)cb1[t] - mean)) + be1[t];
    }
}

// ---------------------------------------------------------------------------
// bn1: BN1-fused affine + relu + cW2 -> g_h2 + BN2 partials; last block
// combines into (alpha2, beta2). 256 blocks x 64 threads (32 rows/block).
// ---------------------------------------------------------------------------
__global__ void __launch_bounds__(64) bn1_kernel(
    const float* __restrict__ cW2, const float* __restrict__ cb2,
    const float* __restrict__ g2, const float* __restrict__ be2)
{
    __shared__ float4 fw1s[32];
    __shared__ float fb1s[32];
    __shared__ float cw2s[16 * 32];
    __shared__ float cb2s[16];
    __shared__ float ovs[32][17];
    __shared__ double redd[32];
    __shared__ int isLast;

    int t = threadIdx.x;
    if (t < 32) { fw1s[t] = g_fw1[t]; fb1s[t] = g_fb1[t]; }
    for (int i = t; i < 512; i += 64) cw2s[i] = cW2[i];
    if (t < 16) cb2s[t] = cb2[t];
    __syncthreads();

    int rl = t >> 1, half = t & 1;
    int row = blockIdx.x * 32 + rl;
    float4 h = ((const float4*)g_h)[row];
    float a[32];
#pragma unroll
    for (int j = 0; j < 32; j++) {
        float4 w = fw1s[j];
        a[j] = fmaxf(w.x * h.x + w.y * h.y + w.z * h.z + w.w * h.w + fb1s[j], 0.f);
    }
    float ov[8];
#pragma unroll
    for (int i = 0; i < 8; i++) {
        int io = half * 8 + i;
        float acc = cb2s[io];
#pragma unroll
        for (int j = 0; j < 32; j++) acc = fmaf(cw2s[io * 32 + j], a[j], acc);
        ov[i] = acc;
        ovs[rl][io] = acc;
    }
    ((float4*)&g_h2[row * 16 + half * 8])[0] = make_float4(ov[0], ov[1], ov[2], ov[3]);
    ((float4*)&g_h2[row * 16 + half * 8])[1] = make_float4(ov[4], ov[5], ov[6], ov[7]);
    __syncthreads();

    if (t < 32) {
        int f = t & 15, kind = t >> 4;
        float s = 0.f;
#pragma unroll
        for (int r = 0; r < 32; r++) {
            float v = ovs[r][f];
            s += kind ? v * v : v;
        }
        g_part2[blockIdx.x * 32 + t] = s;
        __threadfence();
    }
    __syncthreads();
    if (t == 0) {
        int old = atomicAdd(&g_ctr2, 1);
        isLast = (old == 255);
    }
    __syncthreads();
    if (!isLast) return;
    __threadfence();

    // combine2: 32 tasks x 2 threads, 4 independent fp64 chains each
    {
        int task = t >> 1, sub = t & 1;
        double acc[4] = {0.0, 0.0, 0.0, 0.0};
#pragma unroll 4
        for (int i = 0; i < 32; i++) {
#pragma unroll
            for (int c = 0; c < 4; c++) {
                int b = sub + 2 * (c + 4 * i);   // covers 0..255 of parity sub
                acc[c] += (double)g_part2[b * 32 + task];
            }
        }
        double s = (acc[0] + acc[1]) + (acc[2] + acc[3]);
        s += __shfl_xor_sync(FULL, s, 1);
        if (sub == 0) redd[task] = s;
    }
    __syncthreads();
    if (t < 16) {
        double mean = redd[t] / BATCH;
        double var = redd[16 + t] / BATCH - mean * mean;
        float alpha = g2[t] * rsqrtf((float)var + 1e-5f);
        g_ab2[t] = alpha;
        g_ab2[16 + t] = be2[t] - alpha * (float)mean;
    }
}

// ---------------------------------------------------------------------------
// final: BN2-fused affine + relu + cW3 + relu + cW4 + sigmoid -> out.
// 256 blocks x 32 threads.
// ---------------------------------------------------------------------------
__global__ void __launch_bounds__(32) final_kernel(
    const float* __restrict__ cW3, const float* __restrict__ cb3,
    const float* __restrict__ cW4, const float* __restrict__ cb4,
    float* __restrict__ out)
{
    __shared__ float cw3s[128], cb3s[8], cw4s[8], ab2s[32];
    int t = threadIdx.x;
#pragma unroll
    for (int i = t; i < 128; i += 32) cw3s[i] = cW3[i];
    if (t < 8) { cb3s[t] = cb3[t]; cw4s[t] = cW4[t]; }
    ab2s[t] = g_ab2[t];
    __syncthreads();

    int r = blockIdx.x * 32 + t;
    float a[16];
    const float4* hp = (const float4*)&g_h2[r * 16];
#pragma unroll
    for (int j4 = 0; j4 < 4; j4++) {
        float4 v = hp[j4];
        float vv[4] = {v.x, v.y, v.z, v.w};
#pragma unroll
        for (int c = 0; c < 4; c++) {
            int j = j4 * 4 + c;
            a[j] = fmaxf(ab2s[j] * vv[c] + ab2s[16 + j], 0.f);
        }
    }
    float acc4 = cb4[0];
#pragma unroll
    for (int i = 0; i < 8; i++) {
        float acc = cb3s[i];
#pragma unroll
        for (int j = 0; j < 16; j++) acc = fmaf(cw3s[i * 16 + j], a[j], acc);
        acc = fmaxf(acc, 0.f);
        acc4 = fmaf(cw4s[i], acc, acc4);
    }
    out[r] = 1.f / (1.f + expf(-acc4));
}

// ---------------------------------------------------------------------------
extern "C" void kernel_launch(void* const* d_in, const int* in_sizes, int n_in,
                              void* d_out, int out_size) {
    const float* x   = (const float*)d_in[0];
    const float* qw  = (const float*)d_in[1];
    const float* aW  = (const float*)d_in[2];
    const float* ab  = (const float*)d_in[3];
    const float* fW1 = (const float*)d_in[4];
    const float* fb1 = (const float*)d_in[5];
    const float* fW2 = (const float*)d_in[6];
    const float* fb2 = (const float*)d_in[7];
    const float* cW1 = (const float*)d_in[8];
    const float* cb1 = (const float*)d_in[9];
    const float* g1  = (const float*)d_in[10];
    const float* be1 = (const float*)d_in[11];
    const float* cW2 = (const float*)d_in[12];
    const float* cb2 = (const float*)d_in[13];
    const float* g2  = (const float*)d_in[14];
    const float* be2 = (const float*)d_in[15];
    const float* cW3 = (const float*)d_in[16];
    const float* cb3 = (const float*)d_in[17];
    const float* cW4 = (const float*)d_in[18];
    const float* cb4 = (const float*)d_in[19];
    float* out = (float*)d_out;

    prep_kernel<<<33, 256>>>(qw, fW1);
    main_kernel<<<NBLK, 256>>>(x, aW, ab, fb1, fW2, fb2, cW1, cb1, g1, be1);
    bn1_kernel<<<256, 64>>>(cW2, cb2, g2, be2);
    final_kernel<<<256, 32>>>(cW3, cb3, cW4, cb4, out);
}

// round 15
// speedup vs baseline: 1.5050x; 1.5050x over previous
#include <cuda_runtime.h>
#include <cuda_bf16.h>
#include <math.h>
#include <stdint.h>

#define BATCH 8192
#define FULL 0xffffffffu

// ---------------------------------------------------------------------------
// Device scratch (no allocations allowed)
// ---------------------------------------------------------------------------
__device__ __nv_bfloat16 g_Bq_h[512 * 256];  // quantum B [n][k], n=2a(R),2a+1(I)
__device__ __nv_bfloat16 g_Bq_l[512 * 256];
__device__ __nv_bfloat16 g_Bf_h[64 * 256];   // feature B [n][k] = fW1
__device__ __nv_bfloat16 g_Bf_l[64 * 256];
__device__ float  g_gs[BATCH * 16];          // per-row amplitude group sums
__device__ float  g_cf[BATCH * 4];           // tanh feature head
__device__ float  g_h[BATCH * 4];
__device__ float  g_h2[BATCH * 16];
__device__ float  g_part1[64 * 16];          // epi blocks: 14 h-moments
__device__ float  g_part2[256 * 32];         // bn1 blocks: sum/sumsq
__device__ float4 g_fw1[32];
__device__ float  g_fb1f[32];
__device__ float  g_ab2[32];
__device__ int    g_ctr1, g_ctr2;

// ---------------------------------------------------------------------------
// helpers
// ---------------------------------------------------------------------------
__device__ __forceinline__ uint32_t smem_u32(const void* p) {
    uint32_t a;
    asm("{ .reg .u64 t; cvta.to.shared.u64 t, %1; cvt.u32.u64 %0, t; }"
        : "=r"(a) : "l"(p));
    return a;
}
#define SW64(o) ((o) ^ (((o) >> 3) & 0x30))

__device__ __forceinline__ void ldsm4(uint32_t* r, uint32_t addr) {
    asm volatile("ldmatrix.sync.aligned.m8n8.x4.shared.b16 {%0,%1,%2,%3}, [%4];"
        : "=r"(r[0]), "=r"(r[1]), "=r"(r[2]), "=r"(r[3]) : "r"(addr));
}
__device__ __forceinline__ void mma16816(float* d, const uint32_t* a,
                                         uint32_t b0, uint32_t b1) {
    asm volatile("mma.sync.aligned.m16n8k16.row.col.f32.bf16.bf16.f32 "
        "{%0,%1,%2,%3}, {%4,%5,%6,%7}, {%8,%9}, {%0,%1,%2,%3};"
        : "+f"(d[0]), "+f"(d[1]), "+f"(d[2]), "+f"(d[3])
        : "r"(a[0]), "r"(a[1]), "r"(a[2]), "r"(a[3]), "r"(b0), "r"(b1));
}

// ---------------------------------------------------------------------------
// CNOT helpers for circuit sim (lane = amp bits 7..3)
// ---------------------------------------------------------------------------
#define CNOT_LL(cm, tm)                                                        \
    {                                                                          \
        _Pragma("unroll") for (int j = 0; j < 8; j++) {                        \
            float orr = __shfl_xor_sync(FULL, sr[j], (tm));                    \
            float ori = __shfl_xor_sync(FULL, si[j], (tm));                    \
            if (lane & (cm)) { sr[j] = orr; si[j] = ori; }                     \
        }                                                                      \
    }
#define CNOT_LT(cm, mb)                                                        \
    {                                                                          \
        bool f = (lane & (cm)) != 0;                                           \
        _Pragma("unroll") for (int j = 0; j < 8; j++) {                        \
            if (j & (mb)) continue;                                            \
            int j1 = j | (mb);                                                 \
            float t0r = sr[j], t0i = si[j];                                    \
            sr[j] = f ? sr[j1] : sr[j];                                        \
            si[j] = f ? si[j1] : si[j];                                        \
            sr[j1] = f ? t0r : sr[j1];                                         \
            si[j1] = f ? t0i : si[j1];                                         \
        }                                                                      \
    }
#define CNOT_TL(mb, tm)                                                        \
    {                                                                          \
        _Pragma("unroll") for (int j = 0; j < 8; j++) {                        \
            if (!(j & (mb))) continue;                                         \
            sr[j] = __shfl_xor_sync(FULL, sr[j], (tm));                        \
            si[j] = __shfl_xor_sync(FULL, si[j], (tm));                        \
        }                                                                      \
    }
#define CNOT_TT(cmb, tmb)                                                      \
    {                                                                          \
        _Pragma("unroll") for (int j = 0; j < 8; j++) {                        \
            if (!((j & (cmb)) && !(j & (tmb)))) continue;                      \
            int j1 = j | (tmb);                                                \
            float tr = sr[j]; sr[j] = sr[j1]; sr[j1] = tr;                     \
            float ti = si[j]; si[j] = si[j1]; si[j1] = ti;                     \
        }                                                                      \
    }

// ---------------------------------------------------------------------------
// Prep: blocks 0..31 simulate U columns -> split bf16 B rows; block 32
// splits fW1 and zeroes counters.
// ---------------------------------------------------------------------------
__global__ void __launch_bounds__(256) prep_kernel(const float* __restrict__ qw,
                                                   const float* __restrict__ fW1) {
    int t = threadIdx.x;
    if (blockIdx.x == 32) {
        if (t == 0) { g_ctr1 = 0; g_ctr2 = 0; }
        for (int idx = t; idx < 64 * 256; idx += 256) {
            float w = fW1[idx];
            __nv_bfloat16 h = __float2bfloat16(w);
            g_Bf_h[idx] = h;
            g_Bf_l[idx] = __float2bfloat16(w - __bfloat162float(h));
        }
        return;
    }

    __shared__ float s_U[48 * 8];
    if (t < 48) {
        int l = t / 8, q = t % 8;
        float ax = qw[l * 24 + 3 * q + 0] * 0.5f;
        float ay = qw[l * 24 + 3 * q + 1] * 0.5f;
        float az = qw[l * 24 + 3 * q + 2] * 0.5f;
        float cx, sx, cy, sy, cz, sz;
        sincosf(ax, &sx, &cx);
        sincosf(ay, &sy, &cy);
        sincosf(az, &sz, &cz);
        float m00r = cy * cx, m00i = sy * sx;
        float m01r = -sy * cx, m01i = -cy * sx;
        float m10r = sy * cx, m10i = -cy * sx;
        float m11r = cy * cx, m11i = -sy * sx;
        float* u = &s_U[t * 8];
        u[0] = cz * m00r + sz * m00i;  u[1] = cz * m00i - sz * m00r;
        u[2] = cz * m01r + sz * m01i;  u[3] = cz * m01i - sz * m01r;
        u[4] = cz * m10r - sz * m10i;  u[5] = cz * m10i + sz * m10r;
        u[6] = cz * m11r - sz * m11i;  u[7] = cz * m11i + sz * m11r;
    }
    __syncthreads();

    int lane = t & 31;
    int wid = t >> 5;
    int kcol = blockIdx.x * 8 + wid;

    float sr[8], si[8];
#pragma unroll
    for (int j = 0; j < 8; j++) {
        sr[j] = (lane * 8 + j == kcol) ? 1.f : 0.f;
        si[j] = 0.f;
    }

#pragma unroll 1
    for (int l = 0; l < 6; l++) {
        const float* Ul = &s_U[l * 64];
        for (int q = 0; q < 5; q++) {
            const float* u = &Ul[q * 8];
            int m = 16 >> q;
            bool hi = (lane & m) != 0;
            float csr = hi ? u[6] : u[0], csi = hi ? u[7] : u[1];
            float cor = hi ? u[4] : u[2], coi = hi ? u[5] : u[3];
#pragma unroll
            for (int j = 0; j < 8; j++) {
                float orr = __shfl_xor_sync(FULL, sr[j], m);
                float ori = __shfl_xor_sync(FULL, si[j], m);
                float nr = csr * sr[j] - csi * si[j] + cor * orr - coi * ori;
                float ni = csr * si[j] + csi * sr[j] + cor * ori + coi * orr;
                sr[j] = nr; si[j] = ni;
            }
        }
#pragma unroll
        for (int q = 5; q < 8; q++) {
            const float* u = &Ul[q * 8];
            int mb = 1 << (7 - q);
#pragma unroll
            for (int j = 0; j < 8; j++) {
                if (j & mb) continue;
                int j1 = j | mb;
                float ar = sr[j], ai = si[j], br = sr[j1], bi = si[j1];
                sr[j]  = u[0] * ar - u[1] * ai + u[2] * br - u[3] * bi;
                si[j]  = u[0] * ai + u[1] * ar + u[2] * bi + u[3] * br;
                sr[j1] = u[4] * ar - u[5] * ai + u[6] * br - u[7] * bi;
                si[j1] = u[4] * ai + u[5] * ar + u[6] * bi + u[7] * br;
            }
        }
        CNOT_LL(16, 8);
        CNOT_LL(8, 4);
        CNOT_LL(4, 2);
        CNOT_LL(2, 1);
        CNOT_LT(1, 4);
        CNOT_TT(4, 2);
        CNOT_TT(2, 1);
        CNOT_TL(1, 16);
        CNOT_LL(16, 4);
        CNOT_LL(4, 1);
        CNOT_LT(1, 2);
    }

#pragma unroll
    for (int j = 0; j < 8; j++) {
        int a = lane * 8 + j;
        __nv_bfloat16 hr = __float2bfloat16(sr[j]);
        __nv_bfloat16 hi2 = __float2bfloat16(si[j]);
        g_Bq_h[(2 * a) * 256 + kcol] = hr;
        g_Bq_l[(2 * a) * 256 + kcol] = __float2bfloat16(sr[j] - __bfloat162float(hr));
        g_Bq_h[(2 * a + 1) * 256 + kcol] = hi2;
        g_Bq_l[(2 * a + 1) * 256 + kcol] = __float2bfloat16(si[j] - __bfloat162float(hi2));
    }
}

// ---------------------------------------------------------------------------
// GEMM via mma.sync m16n8k16 bf16, 3-term split, K-chunk 32, SW64 smem.
// Warp tile 16 x (NT*8). Quantum: NT=16 (N=128); feature: NT=8 (N=64).
// ---------------------------------------------------------------------------
template <int NT, bool FEAT>
__device__ __forceinline__ void gemm_body(
    char* sAh, char* sAl, char* sBh, char* sBl,
    int mt, int nt, const float* __restrict__ x,
    const float* __restrict__ fb1, const float* __restrict__ fW2,
    const float* __restrict__ fb2)
{
    int t = threadIdx.x, lane = t & 31, wid = t >> 5;
    int m0 = wid * 16;
    uint32_t aAh = smem_u32(sAh), aAl = smem_u32(sAl);
    uint32_t aBh = smem_u32(sBh), aBl = smem_u32(sBl);

    float acc[NT][4];
#pragma unroll
    for (int ni = 0; ni < NT; ni++)
#pragma unroll
        for (int j = 0; j < 4; j++) acc[ni][j] = 0.f;

    const __nv_bfloat16* Bh = FEAT ? g_Bf_h : (g_Bq_h + nt * 128 * 256);
    const __nv_bfloat16* Bl = FEAT ? g_Bf_l : (g_Bq_l + nt * 128 * 256);
    constexpr int NR = NT * 8;

    int ar = t >> 1, akh = (t & 1) * 16;
    int li = lane & 7, lg = lane >> 3;
    // ldmatrix lane-address bases (bytes), row stride 64B
    uint32_t rowA = (uint32_t)((m0 + li + (lg & 1) * 8) * 64 + (lg >> 1) * 16);
    uint32_t rowB = (uint32_t)((li + (lg >> 1) * 8) * 64 + (lg & 1) * 16);

#pragma unroll 1
    for (int c = 0; c < 8; c++) {
        // A: 128 x 32 fp32 -> bf16 hi/lo, SW64 layout
        const float4* xp = (const float4*)(x + (mt * 128 + ar) * 256 + c * 32 + akh);
#pragma unroll
        for (int i = 0; i < 4; i++) {
            float4 v = xp[i];
            __nv_bfloat162 h01 = __floats2bfloat162_rn(v.x, v.y);
            __nv_bfloat162 h23 = __floats2bfloat162_rn(v.z, v.w);
            __nv_bfloat162 l01 = __floats2bfloat162_rn(
                v.x - __bfloat162float(h01.x), v.y - __bfloat162float(h01.y));
            __nv_bfloat162 l23 = __floats2bfloat162_rn(
                v.z - __bfloat162float(h23.x), v.w - __bfloat162float(h23.y));
            uint32_t off = SW64((uint32_t)(ar * 64 + (akh + i * 4) * 2));
            *(uint2*)(sAh + off) = make_uint2(*(uint32_t*)&h01, *(uint32_t*)&h23);
            *(uint2*)(sAl + off) = make_uint2(*(uint32_t*)&l01, *(uint32_t*)&l23);
        }
        // B: NR x 32 bf16 hi/lo
        for (int i = t; i < NR * 4; i += 256) {
            int nl = i >> 2;
            int k8 = (i & 3) * 8;
            uint4 vh = *(const uint4*)(Bh + nl * 256 + c * 32 + k8);
            uint4 vl = *(const uint4*)(Bl + nl * 256 + c * 32 + k8);
            uint32_t off = SW64((uint32_t)(nl * 64 + k8 * 2));
            *(uint4*)(sBh + off) = vh;
            *(uint4*)(sBl + off) = vl;
        }
        __syncthreads();

#pragma unroll
        for (int ks = 0; ks < 2; ks++) {
            uint32_t kb = ks * 32;
            uint32_t ah[4], al[4];
            ldsm4(ah, aAh + SW64(rowA + kb));
            ldsm4(al, aAl + SW64(rowA + kb));
#pragma unroll
            for (int np = 0; np < NT / 2; np++) {
                uint32_t bh[4], bl[4];
                uint32_t ro = rowB + (uint32_t)(np * 1024) + kb;  // 16 rows * 64B
                ldsm4(bh, aBh + SW64(ro));
                ldsm4(bl, aBl + SW64(ro));
                mma16816(acc[2 * np],     ah, bh[0], bh[1]);
                mma16816(acc[2 * np + 1], ah, bh[2], bh[3]);
                mma16816(acc[2 * np],     ah, bl[0], bl[1]);
                mma16816(acc[2 * np + 1], ah, bl[2], bl[3]);
                mma16816(acc[2 * np],     al, bh[0], bh[1]);
                mma16816(acc[2 * np + 1], al, bh[2], bh[3]);
            }
        }
        __syncthreads();
    }

    // Epilogue. Thread covers rows m0 + lane/4 + {0,8}; cols ni*8 + 2*(lane&3)+{0,1}.
    if (!FEAT) {
        float gsum[2][4];
#pragma unroll
        for (int h = 0; h < 2; h++)
#pragma unroll
            for (int g = 0; g < 4; g++) gsum[h][g] = 0.f;
#pragma unroll
        for (int ni = 0; ni < NT; ni++) {
            int g = ni >> 2;
#pragma unroll
            for (int h = 0; h < 2; h++) {
                float re = acc[ni][2 * h], im = acc[ni][2 * h + 1];
                gsum[h][g] += re * re + im * im;
            }
        }
#pragma unroll
        for (int h = 0; h < 2; h++)
#pragma unroll
            for (int g = 0; g < 4; g++) {
                gsum[h][g] += __shfl_xor_sync(FULL, gsum[h][g], 1);
                gsum[h][g] += __shfl_xor_sync(FULL, gsum[h][g], 2);
            }
        if ((lane & 3) == 0) {
#pragma unroll
            for (int h = 0; h < 2; h++) {
                int row = mt * 128 + m0 + (lane >> 2) + 8 * h;
                *(float4*)&g_gs[row * 16 + nt * 4] =
                    make_float4(gsum[h][0], gsum[h][1], gsum[h][2], gsum[h][3]);
            }
        }
    } else {
        float d[2][4];
#pragma unroll
        for (int h = 0; h < 2; h++)
#pragma unroll
            for (int i = 0; i < 4; i++) d[h][i] = 0.f;
        int cq = 2 * (lane & 3);
#pragma unroll
        for (int ni = 0; ni < NT; ni++) {
            int c0 = ni * 8 + cq;
            float b0 = __ldg(&fb1[c0]), b1 = __ldg(&fb1[c0 + 1]);
#pragma unroll
            for (int h = 0; h < 2; h++) {
                float a0 = fmaxf(acc[ni][2 * h] + b0, 0.f);
                float a1 = fmaxf(acc[ni][2 * h + 1] + b1, 0.f);
#pragma unroll
                for (int i = 0; i < 4; i++)
                    d[h][i] += a0 * __ldg(&fW2[i * 64 + c0])
                             + a1 * __ldg(&fW2[i * 64 + c0 + 1]);
            }
        }
#pragma unroll
        for (int h = 0; h < 2; h++)
#pragma unroll
            for (int i = 0; i < 4; i++) {
                d[h][i] += __shfl_xor_sync(FULL, d[h][i], 1);
                d[h][i] += __shfl_xor_sync(FULL, d[h][i], 2);
            }
        if ((lane & 3) == 0) {
#pragma unroll
            for (int h = 0; h < 2; h++) {
                int row = mt * 128 + m0 + (lane >> 2) + 8 * h;
                ((float4*)g_cf)[row] = make_float4(
                    tanhf(d[h][0] + fb2[0]), tanhf(d[h][1] + fb2[1]),
                    tanhf(d[h][2] + fb2[2]), tanhf(d[h][3] + fb2[3]));
            }
        }
    }
}

__global__ void __launch_bounds__(256) gemm_kernel(
    const float* __restrict__ x,
    const float* __restrict__ fb1, const float* __restrict__ fW2,
    const float* __restrict__ fb2)
{
    __shared__ __align__(16) char sAh[128 * 64];
    __shared__ __align__(16) char sAl[128 * 64];
    __shared__ __align__(16) char sBh[128 * 64];
    __shared__ __align__(16) char sBl[128 * 64];
    int nt = blockIdx.x >> 6;
    int mt = blockIdx.x & 63;
    if (nt == 4)
        gemm_body<8, true>(sAh, sAl, sBh, sBl, mt, nt, x, fb1, fW2, fb2);
    else
        gemm_body<16, false>(sAh, sAl, sBh, sBl, mt, nt, x, fb1, fW2, fb2);
}

// ---------------------------------------------------------------------------
// epi: gs -> z -> h (+cf) -> moments; last block makes BN1-fused weights.
// 64 blocks x 128 threads.
// ---------------------------------------------------------------------------
__global__ void __launch_bounds__(128) epi_kernel(
    const float* __restrict__ aW, const float* __restrict__ ab,
    const float* __restrict__ cW1, const float* __restrict__ cb1,
    const float* __restrict__ g1, const float* __restrict__ be1)
{
    __shared__ float wp[4][14];
    __shared__ double mom[14];
    __shared__ int isLast;
    int t = threadIdx.x, lane = t & 31, wid = t >> 5;
    int row = blockIdx.x * 128 + t;

    float gs[16];
    const float4* gp = (const float4*)(g_gs + row * 16);
#pragma unroll
    for (int i = 0; i < 4; i++) {
        float4 v = gp[i];
        gs[4 * i] = v.x; gs[4 * i + 1] = v.y; gs[4 * i + 2] = v.z; gs[4 * i + 3] = v.w;
    }
    float S = 0.f;
#pragma unroll
    for (int g = 0; g < 16; g++) S += gs[g];
    float invS = 1.f / S;
    float z[4];
#pragma unroll
    for (int w = 0; w < 4; w++) {
        float num = 0.f;
#pragma unroll
        for (int g = 0; g < 16; g++)
            num += ((g >> (3 - w)) & 1) ? -gs[g] : gs[g];
        z[w] = num * invS;
    }
    float4 cf = ((const float4*)g_cf)[row];
    float h[4];
#pragma unroll
    for (int i = 0; i < 4; i++)
        h[i] = ab[i] + aW[i * 4] * z[0] + aW[i * 4 + 1] * z[1]
                     + aW[i * 4 + 2] * z[2] + aW[i * 4 + 3] * z[3]
             + ((const float*)&cf)[i];
    ((float4*)g_h)[row] = make_float4(h[0], h[1], h[2], h[3]);

    float m[14] = {h[0], h[1], h[2], h[3],
                   h[0] * h[0], h[0] * h[1], h[0] * h[2], h[0] * h[3],
                   h[1] * h[1], h[1] * h[2], h[1] * h[3],
                   h[2] * h[2], h[2] * h[3], h[3] * h[3]};
#pragma unroll
    for (int v = 0; v < 14; v++) {
        float s = m[v];
#pragma unroll
        for (int o = 16; o; o >>= 1) s += __shfl_xor_sync(FULL, s, o);
        if (lane == 0) wp[wid][v] = s;
    }
    __syncthreads();
    if (t < 14)
        g_part1[blockIdx.x * 16 + t] = wp[0][t] + wp[1][t] + wp[2][t] + wp[3][t];
    if (t == 0) {
        __threadfence();
        int old = atomicAdd(&g_ctr1, 1);
        isLast = (old == 63);
    }
    __syncthreads();
    if (!isLast) return;
    __threadfence();

    // combine 14 moments over 64 blocks — FULL-WARP shuffles only:
    // warp wid handles moments m = wid, wid+4, ... ; each lane sums 2 blocks.
    for (int m2 = wid; m2 < 14; m2 += 4) {
        double s = (double)g_part1[lane * 16 + m2]
                 + (double)g_part1[(lane + 32) * 16 + m2];
#pragma unroll
        for (int o = 16; o; o >>= 1) s += __shfl_xor_sync(FULL, s, o);
        if (lane == 0) mom[m2] = s;
    }
    __syncthreads();
    if (t < 32) {
        double invB = 1.0 / BATCH;
        double mu[4];
#pragma unroll
        for (int i = 0; i < 4; i++) mu[i] = mom[i] * invB;
        double C[4][4];
        const int pi[10] = {0, 0, 0, 0, 1, 1, 1, 2, 2, 3};
        const int pj[10] = {0, 1, 2, 3, 1, 2, 3, 2, 3, 3};
#pragma unroll
        for (int p = 0; p < 10; p++) {
            double c = mom[4 + p] * invB - mu[pi[p]] * mu[pj[p]];
            C[pi[p]][pj[p]] = c;
            C[pj[p]][pi[p]] = c;
        }
        double w[4];
#pragma unroll
        for (int i = 0; i < 4; i++) w[i] = (double)cW1[t * 4 + i];
        double mean = (double)cb1[t];
        double var = 0.0;
#pragma unroll
        for (int i = 0; i < 4; i++) {
            mean += w[i] * mu[i];
#pragma unroll
            for (int j = 0; j < 4; j++) var += w[i] * w[j] * C[i][j];
        }
        float alpha = g1[t] * rsqrtf((float)var + 1e-5f);
        float4 w1 = ((const float4*)cW1)[t];
        g_fw1[t] = make_float4(alpha * w1.x, alpha * w1.y, alpha * w1.z, alpha * w1.w);
        g_fb1f[t] = alpha * ((float)((double)cb1[t] - mean)) + be1[t];
    }
}

// ---------------------------------------------------------------------------
// bn1: fused affine + relu + cW2 -> g_h2 + partials; last block -> ab2.
// 256 blocks x 64 threads.
// ---------------------------------------------------------------------------
__global__ void __launch_bounds__(64) bn1_kernel(
    const float* __restrict__ cW2, const float* __restrict__ cb2,
    const float* __restrict__ g2, const float* __restrict__ be2)
{
    __shared__ float4 fw1s[32];
    __shared__ float fb1s[32];
    __shared__ float cw2s[16 * 32];
    __shared__ float cb2s[16];
    __shared__ float ovs[32][17];
    __shared__ double redd[32];
    __shared__ int isLast;

    int t = threadIdx.x;
    if (t < 32) { fw1s[t] = g_fw1[t]; fb1s[t] = g_fb1f[t]; }
    for (int i = t; i < 512; i += 64) cw2s[i] = cW2[i];
    if (t < 16) cb2s[t] = cb2[t];
    __syncthreads();

    int rl = t >> 1, half = t & 1;
    int row = blockIdx.x * 32 + rl;
    float4 h = ((const float4*)g_h)[row];
    float a[32];
#pragma unroll
    for (int j = 0; j < 32; j++) {
        float4 w = fw1s[j];
        a[j] = fmaxf(w.x * h.x + w.y * h.y + w.z * h.z + w.w * h.w + fb1s[j], 0.f);
    }
    float ov[8];
#pragma unroll
    for (int i = 0; i < 8; i++) {
        int io = half * 8 + i;
        float acc = cb2s[io];
#pragma unroll
        for (int j = 0; j < 32; j++) acc = fmaf(cw2s[io * 32 + j], a[j], acc);
        ov[i] = acc;
        ovs[rl][io] = acc;
    }
    ((float4*)&g_h2[row * 16 + half * 8])[0] = make_float4(ov[0], ov[1], ov[2], ov[3]);
    ((float4*)&g_h2[row * 16 + half * 8])[1] = make_float4(ov[4], ov[5], ov[6], ov[7]);
    __syncthreads();

    if (t < 32) {
        int f = t & 15, kind = t >> 4;
        float s = 0.f;
#pragma unroll
        for (int r = 0; r < 32; r++) {
            float v = ovs[r][f];
            s += kind ? v * v : v;
        }
        g_part2[blockIdx.x * 32 + t] = s;
        __threadfence();
    }
    __syncthreads();
    if (t == 0) {
        int old = atomicAdd(&g_ctr2, 1);
        isLast = (old == 255);
    }
    __syncthreads();
    if (!isLast) return;
    __threadfence();

    {
        int task = t >> 1, sub = t & 1;
        double acc[4] = {0.0, 0.0, 0.0, 0.0};
#pragma unroll 4
        for (int i = 0; i < 32; i++) {
#pragma unroll
            for (int c = 0; c < 4; c++) {
                int b = sub + 2 * (c + 4 * i);
                acc[c] += (double)g_part2[b * 32 + task];
            }
        }
        double s = (acc[0] + acc[1]) + (acc[2] + acc[3]);
        s += __shfl_xor_sync(FULL, s, 1);
        if (sub == 0) redd[task] = s;
    }
    __syncthreads();
    if (t < 16) {
        double mean = redd[t] / BATCH;
        double var = redd[16 + t] / BATCH - mean * mean;
        float alpha = g2[t] * rsqrtf((float)var + 1e-5f);
        g_ab2[t] = alpha;
        g_ab2[16 + t] = be2[t] - alpha * (float)mean;
    }
}

// ---------------------------------------------------------------------------
// final: fused BN2 + relu + cW3 + relu + cW4 + sigmoid. 256 x 32.
// ---------------------------------------------------------------------------
__global__ void __launch_bounds__(32) final_kernel(
    const float* __restrict__ cW3, const float* __restrict__ cb3,
    const float* __restrict__ cW4, const float* __restrict__ cb4,
    float* __restrict__ out)
{
    __shared__ float cw3s[128], cb3s[8], cw4s[8], ab2s[32];
    int t = threadIdx.x;
#pragma unroll
    for (int i = t; i < 128; i += 32) cw3s[i] = cW3[i];
    if (t < 8) { cb3s[t] = cb3[t]; cw4s[t] = cW4[t]; }
    ab2s[t] = g_ab2[t];
    __syncthreads();

    int r = blockIdx.x * 32 + t;
    float a[16];
    const float4* hp = (const float4*)&g_h2[r * 16];
#pragma unroll
    for (int j4 = 0; j4 < 4; j4++) {
        float4 v = hp[j4];
        float vv[4] = {v.x, v.y, v.z, v.w};
#pragma unroll
        for (int c = 0; c < 4; c++) {
            int j = j4 * 4 + c;
            a[j] = fmaxf(ab2s[j] * vv[c] + ab2s[16 + j], 0.f);
        }
    }
    float acc4 = cb4[0];
#pragma unroll
    for (int i = 0; i < 8; i++) {
        float acc = cb3s[i];
#pragma unroll
        for (int j = 0; j < 16; j++) acc = fmaf(cw3s[i * 16 + j], a[j], acc);
        acc = fmaxf(acc, 0.f);
        acc4 = fmaf(cw4s[i], acc, acc4);
    }
    out[r] = 1.f / (1.f + expf(-acc4));
}

// ---------------------------------------------------------------------------
extern "C" void kernel_launch(void* const* d_in, const int* in_sizes, int n_in,
                              void* d_out, int out_size) {
    const float* x   = (const float*)d_in[0];
    const float* qw  = (const float*)d_in[1];
    const float* aW  = (const float*)d_in[2];
    const float* ab  = (const float*)d_in[3];
    const float* fW1 = (const float*)d_in[4];
    const float* fb1 = (const float*)d_in[5];
    const float* fW2 = (const float*)d_in[6];
    const float* fb2 = (const float*)d_in[7];
    const float* cW1 = (const float*)d_in[8];
    const float* cb1 = (const float*)d_in[9];
    const float* g1  = (const float*)d_in[10];
    const float* be1 = (const float*)d_in[11];
    const float* cW2 = (const float*)d_in[12];
    const float* cb2 = (const float*)d_in[13];
    const float* g2  = (const float*)d_in[14];
    const float* be2 = (const float*)d_in[15];
    const float* cW3 = (const float*)d_in[16];
    const float* cb3 = (const float*)d_in[17];
    const float* cW4 = (const float*)d_in[18];
    const float* cb4 = (const float*)d_in[19];
    float* out = (float*)d_out;

    prep_kernel<<<33, 256>>>(qw, fW1);
    gemm_kernel<<<320, 256>>>(x, fb1, fW2, fb2);
    epi_kernel<<<64, 128>>>(aW, ab, cW1, cb1, g1, be1);
    bn1_kernel<<<256, 64>>>(cW2, cb2, g2, be2);
    final_kernel<<<256, 32>>>(cW3, cb3, cW4, cb4, out);
}